// round 6
// baseline (speedup 1.0000x reference)
#include <cuda_runtime.h>
#include <math.h>

// Problem constants
#define N_IMG 4
#define C_DIM 256
#define H_DIM 50
#define W_DIM 50
#define HW (H_DIM * W_DIM)
#define PH 7
#define PW 7
#define NBINS (PH * PW)
#define N_ROI 1024
#define OUT_PER_ROI (C_DIM * NBINS)   // 12544 floats
#define SPATIAL_SCALE 0.0625f
#define ROW_STRIDE (W_DIM * C_DIM)    // floats per h-row in NHWC

// fl(1/7) in fp32 — XLA rewrites (x / 7) into (x * fl(1/7)); we must match it.
#define RCP_7 0.14285714924335479736328125f

// Scratch: x transposed to [N][H][W][C] (channels-last) = 10.24 MB
__device__ float g_xt[N_IMG * HW * C_DIM];

// ---------------------------------------------------------------------------
// Transpose NCHW -> NHWC via 32x32 smem tiles.
// ---------------------------------------------------------------------------
__global__ void __launch_bounds__(1024) transpose_kernel(const float* __restrict__ x) {
    __shared__ float tile[32][33];
    const int n = blockIdx.z;
    const int hw0 = blockIdx.x * 32;
    const int c0  = blockIdx.y * 32;

    {
        const int c  = c0 + threadIdx.y;
        const int hw = hw0 + threadIdx.x;
        if (hw < HW) {
            tile[threadIdx.y][threadIdx.x] = x[(n * C_DIM + c) * HW + hw];
        }
    }
    __syncthreads();
    {
        const int hw = hw0 + threadIdx.y;
        const int c  = c0 + threadIdx.x;
        if (hw < HW) {
            g_xt[(n * HW + hw) * C_DIM + c] = tile[threadIdx.x][threadIdx.y];
        }
    }
}

// ---------------------------------------------------------------------------
// RoI max pooling: one block per (roi, ph-row). Grid = 1024 x 7.
// Block = 256 threads = 4 pw-groups x 64 lanes (float4 -> 256 channels).
// Each thread owns TWO bins (pwA = grp, pwB = grp + 4) and processes BOTH
// inside a single h-sweep, unrolled x2 in w -> 4-8 independent LDG.128 in
// flight per h iteration (latency hiding against ~240cyc L2 hits).
//
// Bin boundaries emulate XLA numerics exactly:
//   bh = rh * fl(1/7)   (reciprocal-multiply, NOT true division)
//   edges = floor/ceil of single fp32 multiplies (__fmul_rn: no contraction)
// ---------------------------------------------------------------------------
__global__ void __launch_bounds__(256, 6) roipool_kernel(const float* __restrict__ rois,
                                                         float* __restrict__ out) {
    __shared__ float s_out[C_DIM * PW];   // [c][pw] = 7168 B

    const int roi = blockIdx.x;
    const int ph  = blockIdx.y;
    const float* r = rois + roi * 5;

    const int b  = (int)r[0];
    const int xs = (int)rintf(__fmul_rn(r[1], SPATIAL_SCALE));
    const int ys = (int)rintf(__fmul_rn(r[2], SPATIAL_SCALE));
    const int xe = (int)rintf(__fmul_rn(r[3], SPATIAL_SCALE));
    const int ye = (int)rintf(__fmul_rn(r[4], SPATIAL_SCALE));

    const float rw = (float)max(xe - xs + 1, 1);
    const float rh = (float)max(ye - ys + 1, 1);
    const float bh = __fmul_rn(rh, RCP_7);   // match XLA numerics
    const float bw = __fmul_rn(rw, RCP_7);

    int hs = (int)floorf(__fmul_rn((float)ph,        bh)) + ys;
    int he = (int)ceilf (__fmul_rn((float)ph + 1.0f, bh)) + ys;
    hs = min(max(hs, 0), H_DIM);
    he = min(max(he, 0), H_DIM);

    const int lane = threadIdx.x & 63;   // 64 lanes -> 256 channels via float4
    const int grp  = threadIdx.x >> 6;   // 4 pw-groups
    const int c0   = lane * 4;

    // Bin A: pw = grp (always valid). Bin B: pw = grp + 4 (invalid for grp=3).
    const int pwA = grp;
    const int pwB = grp + 4;

    int wsA = (int)floorf(__fmul_rn((float)pwA,        bw)) + xs;
    int weA = (int)ceilf (__fmul_rn((float)pwA + 1.0f, bw)) + xs;
    wsA = min(max(wsA, 0), W_DIM);
    weA = min(max(weA, 0), W_DIM);

    int wsB = 0, weB = 0;
    if (pwB < PW) {
        wsB = (int)floorf(__fmul_rn((float)pwB,        bw)) + xs;
        weB = (int)ceilf (__fmul_rn((float)pwB + 1.0f, bw)) + xs;
        wsB = min(max(wsB, 0), W_DIM);
        weB = min(max(weB, 0), W_DIM);
    }

    const bool emptyA = (hs >= he) || (wsA >= weA);
    const bool emptyB = (hs >= he) || (wsB >= weB);

    float a0 = -INFINITY, a1 = -INFINITY, a2 = -INFINITY, a3 = -INFINITY;
    float b0 = -INFINITY, b1 = -INFINITY, b2 = -INFINITY, b3 = -INFINITY;

    const float* rowp = g_xt + (size_t)b * HW * C_DIM + (size_t)hs * ROW_STRIDE + c0;

    #pragma unroll 1
    for (int h = hs; h < he; ++h, rowp += ROW_STRIDE) {
        // ---- bin A loads (unroll x2) ----
        int w = wsA;
        for (; w + 1 < weA; w += 2) {
            const float4 v0 = *(const float4*)(rowp + w * C_DIM);
            const float4 v1 = *(const float4*)(rowp + (w + 1) * C_DIM);
            a0 = fmaxf(fmaxf(a0, v0.x), v1.x);
            a1 = fmaxf(fmaxf(a1, v0.y), v1.y);
            a2 = fmaxf(fmaxf(a2, v0.z), v1.z);
            a3 = fmaxf(fmaxf(a3, v0.w), v1.w);
        }
        if (w < weA) {
            const float4 v = *(const float4*)(rowp + w * C_DIM);
            a0 = fmaxf(a0, v.x); a1 = fmaxf(a1, v.y);
            a2 = fmaxf(a2, v.z); a3 = fmaxf(a3, v.w);
        }
        // ---- bin B loads (unroll x2), independent of A -> more MLP ----
        w = wsB;
        for (; w + 1 < weB; w += 2) {
            const float4 v0 = *(const float4*)(rowp + w * C_DIM);
            const float4 v1 = *(const float4*)(rowp + (w + 1) * C_DIM);
            b0 = fmaxf(fmaxf(b0, v0.x), v1.x);
            b1 = fmaxf(fmaxf(b1, v0.y), v1.y);
            b2 = fmaxf(fmaxf(b2, v0.z), v1.z);
            b3 = fmaxf(fmaxf(b3, v0.w), v1.w);
        }
        if (w < weB) {
            const float4 v = *(const float4*)(rowp + w * C_DIM);
            b0 = fmaxf(b0, v.x); b1 = fmaxf(b1, v.y);
            b2 = fmaxf(b2, v.z); b3 = fmaxf(b3, v.w);
        }
    }

    if (emptyA) { a0 = a1 = a2 = a3 = 0.0f; }
    s_out[(c0 + 0) * PW + pwA] = a0;
    s_out[(c0 + 1) * PW + pwA] = a1;
    s_out[(c0 + 2) * PW + pwA] = a2;
    s_out[(c0 + 3) * PW + pwA] = a3;

    if (pwB < PW) {
        if (emptyB) { b0 = b1 = b2 = b3 = 0.0f; }
        s_out[(c0 + 0) * PW + pwB] = b0;
        s_out[(c0 + 1) * PW + pwB] = b1;
        s_out[(c0 + 2) * PW + pwB] = b2;
        s_out[(c0 + 3) * PW + pwB] = b3;
    }
    __syncthreads();

    // Store: out[roi, c, ph, pw] = s_out[c*7 + pw].
    float* __restrict__ obase = out + (size_t)roi * OUT_PER_ROI + ph * PW;
    #pragma unroll 1
    for (int i = threadIdx.x; i < C_DIM * PW; i += 256) {
        const int c  = i / PW;
        const int pw = i - c * PW;
        obase[c * NBINS + pw] = s_out[i];
    }
}

extern "C" void kernel_launch(void* const* d_in, const int* in_sizes, int n_in,
                              void* d_out, int out_size) {
    const float* x    = (const float*)d_in[0];
    const float* rois = (const float*)d_in[1];
    float* out        = (float*)d_out;

    (void)in_sizes; (void)n_in; (void)out_size;

    dim3 tgrid((HW + 31) / 32, C_DIM / 32, N_IMG);
    dim3 tblk(32, 32);
    transpose_kernel<<<tgrid, tblk>>>(x);

    dim3 pgrid(N_ROI, PH);
    roipool_kernel<<<pgrid, 256>>>(rois, out);
}

// round 7
// speedup vs baseline: 1.0856x; 1.0856x over previous
#include <cuda_runtime.h>
#include <math.h>

// Problem constants
#define N_IMG 4
#define C_DIM 256
#define H_DIM 50
#define W_DIM 50
#define HW (H_DIM * W_DIM)
#define PH 7
#define PW 7
#define NBINS (PH * PW)
#define N_ROI 1024
#define OUT_PER_ROI (C_DIM * NBINS)   // 12544 floats
#define SPATIAL_SCALE 0.0625f
#define ROW_STRIDE (W_DIM * C_DIM)    // floats per h-row in NHWC

// fl(1/7) in fp32 — XLA rewrites (x / 7) into (x * fl(1/7)); we must match it.
#define RCP_7 0.14285714924335479736328125f

// Scratch: x transposed to [N][H][W][C] (channels-last) = 10.24 MB
__device__ float g_xt[N_IMG * HW * C_DIM];

// Precomputed per-roi geometry (ints, computed once with exact XLA numerics)
__device__ int g_boff[N_ROI];        // image base offset in floats
__device__ int g_hs[N_ROI * PH];
__device__ int g_he[N_ROI * PH];
__device__ int g_ws[N_ROI * PW];
__device__ int g_we[N_ROI * PW];

// ---------------------------------------------------------------------------
// Transpose NCHW -> NHWC via 32x32 smem tiles.
// Block (0,0,0) additionally precomputes all roi bin edges (1024 threads =
// 1024 rois) — zero extra launch, exact XLA numerics isolated here.
// ---------------------------------------------------------------------------
__global__ void __launch_bounds__(1024) transpose_kernel(const float* __restrict__ x,
                                                         const float* __restrict__ rois) {
    __shared__ float tile[32][33];

    if (blockIdx.x == 0 && blockIdx.y == 0 && blockIdx.z == 0) {
        const int roi = threadIdx.y * 32 + threadIdx.x;   // 0..1023
        const float* r = rois + roi * 5;
        const int b  = (int)r[0];
        const int xs = (int)rintf(__fmul_rn(r[1], SPATIAL_SCALE));
        const int ys = (int)rintf(__fmul_rn(r[2], SPATIAL_SCALE));
        const int xe = (int)rintf(__fmul_rn(r[3], SPATIAL_SCALE));
        const int ye = (int)rintf(__fmul_rn(r[4], SPATIAL_SCALE));
        const float rw = (float)max(xe - xs + 1, 1);
        const float rh = (float)max(ye - ys + 1, 1);
        const float bh = __fmul_rn(rh, RCP_7);   // XLA reciprocal-multiply
        const float bw = __fmul_rn(rw, RCP_7);

        g_boff[roi] = b * (HW * C_DIM);
        #pragma unroll
        for (int p = 0; p < PH; ++p) {
            int hs = (int)floorf(__fmul_rn((float)p,        bh)) + ys;
            int he = (int)ceilf (__fmul_rn((float)p + 1.0f, bh)) + ys;
            int ws = (int)floorf(__fmul_rn((float)p,        bw)) + xs;
            int we = (int)ceilf (__fmul_rn((float)p + 1.0f, bw)) + xs;
            g_hs[roi * PH + p] = min(max(hs, 0), H_DIM);
            g_he[roi * PH + p] = min(max(he, 0), H_DIM);
            g_ws[roi * PW + p] = min(max(ws, 0), W_DIM);
            g_we[roi * PW + p] = min(max(we, 0), W_DIM);
        }
    }

    const int n   = blockIdx.z;
    const int hw0 = blockIdx.x * 32;
    const int c0b = blockIdx.y * 32;
    {
        const int c  = c0b + threadIdx.y;
        const int hw = hw0 + threadIdx.x;
        if (hw < HW) {
            tile[threadIdx.y][threadIdx.x] = x[(n * C_DIM + c) * HW + hw];
        }
    }
    __syncthreads();
    {
        const int hw = hw0 + threadIdx.y;
        const int c  = c0b + threadIdx.x;
        if (hw < HW) {
            g_xt[(n * HW + hw) * C_DIM + c] = tile[threadIdx.x][threadIdx.y];
        }
    }
}

// ---------------------------------------------------------------------------
// RoI max pooling: one block per (roi, ph-row). Grid = 1024 x 7.
// Block = 256 threads = 4 pw-groups x 64 lanes (float4 -> 256 channels).
// Each pw-group handles pw = grp, then pw = grp + 4 (R5 structure).
// Prologue is 5 independent int loads from precomputed tables — no FP math,
// minimal registers -> 8 CTAs/SM (100% warp occupancy).
// ---------------------------------------------------------------------------
__global__ void __launch_bounds__(256, 8) roipool_kernel(float* __restrict__ out) {
    __shared__ float s_out[C_DIM * PW];   // [c][pw] = 7168 B

    const int roi = blockIdx.x;
    const int ph  = blockIdx.y;

    const int boff = __ldg(&g_boff[roi]);
    const int hs   = __ldg(&g_hs[roi * PH + ph]);
    const int he   = __ldg(&g_he[roi * PH + ph]);

    const int lane = threadIdx.x & 63;   // 64 lanes -> 256 channels via float4
    const int grp  = threadIdx.x >> 6;   // 4 pw-groups
    const int c0   = lane * 4;

    const float* __restrict__ base = g_xt + boff + c0;

    #pragma unroll 1
    for (int it = 0; it < 2; ++it) {
        const int pw = it * 4 + grp;
        if (pw < PW) {
            const int ws = __ldg(&g_ws[roi * PW + pw]);
            const int we = __ldg(&g_we[roi * PW + pw]);

            float m0 = -INFINITY, m1 = -INFINITY, m2 = -INFINITY, m3 = -INFINITY;
            const bool empty = (hs >= he) || (ws >= we);

            #pragma unroll 1
            for (int h = hs; h < he; ++h) {
                const float* rowp = base + h * ROW_STRIDE;
                int w = ws;
                for (; w + 1 < we; w += 2) {   // 2 independent loads in flight
                    const float4 v0 = *(const float4*)(rowp + w * C_DIM);
                    const float4 v1 = *(const float4*)(rowp + (w + 1) * C_DIM);
                    m0 = fmaxf(fmaxf(m0, v0.x), v1.x);
                    m1 = fmaxf(fmaxf(m1, v0.y), v1.y);
                    m2 = fmaxf(fmaxf(m2, v0.z), v1.z);
                    m3 = fmaxf(fmaxf(m3, v0.w), v1.w);
                }
                if (w < we) {
                    const float4 v = *(const float4*)(rowp + w * C_DIM);
                    m0 = fmaxf(m0, v.x); m1 = fmaxf(m1, v.y);
                    m2 = fmaxf(m2, v.z); m3 = fmaxf(m3, v.w);
                }
            }
            if (empty) { m0 = m1 = m2 = m3 = 0.0f; }

            s_out[(c0 + 0) * PW + pw] = m0;
            s_out[(c0 + 1) * PW + pw] = m1;
            s_out[(c0 + 2) * PW + pw] = m2;
            s_out[(c0 + 3) * PW + pw] = m3;
        }
    }
    __syncthreads();

    // Store: out[roi, c, ph, pw] = s_out[c*7 + pw].
    float* __restrict__ obase = out + (size_t)roi * OUT_PER_ROI + ph * PW;
    #pragma unroll 1
    for (int i = threadIdx.x; i < C_DIM * PW; i += 256) {
        const int c  = i / PW;
        const int pw = i - c * PW;
        obase[c * NBINS + pw] = s_out[i];
    }
}

extern "C" void kernel_launch(void* const* d_in, const int* in_sizes, int n_in,
                              void* d_out, int out_size) {
    const float* x    = (const float*)d_in[0];
    const float* rois = (const float*)d_in[1];
    float* out        = (float*)d_out;

    (void)in_sizes; (void)n_in; (void)out_size;

    dim3 tgrid((HW + 31) / 32, C_DIM / 32, N_IMG);
    dim3 tblk(32, 32);
    transpose_kernel<<<tgrid, tblk>>>(x, rois);

    dim3 pgrid(N_ROI, PH);
    roipool_kernel<<<pgrid, 256>>>(out);
}